// round 2
// baseline (speedup 1.0000x reference)
#include <cuda_runtime.h>
#include <math.h>

// Problem constants
#define TSEQ   2048
#define HID    2048
#define QDIM   4096   // 2*HIDDEN (q projection width; 32 rope-heads * 128)
#define KVDIM  1024   // 8 kv heads * 128
#define HD     128
#define NH16   16
#define NKV    8
#define HQ     32

// Scratch (static __device__ — no allocations allowed)
__device__ float g_q  [TSEQ * QDIM];
__device__ float g_k  [TSEQ * KVDIM];
__device__ float g_v  [TSEQ * KVDIM];
__device__ float g_qr [TSEQ * QDIM];
__device__ float g_kr [TSEQ * KVDIM];
__device__ float g_att[TSEQ * QDIM];

// ---------------------------------------------------------------------------
// SGEMM: C[M,N] = A[M,K] @ B[K,N], row-major, fp32.
// 128x128 block tile, BK=8, 256 threads, 8x8 microtile per thread.
// ---------------------------------------------------------------------------
#define GBM 128
#define GBN 128
#define GBK 8

__global__ __launch_bounds__(256) void sgemm_kernel(
    const float* __restrict__ A, const float* __restrict__ B,
    float* __restrict__ C, int M, int N, int K)
{
    __shared__ float As[GBK][GBM + 4];
    __shared__ float Bs[GBK][GBN + 4];

    const int tid = threadIdx.x;
    const int tx  = tid & 15;        // 0..15  (n dir)
    const int ty  = tid >> 4;        // 0..15  (m dir)
    const int m0  = blockIdx.y * GBM;
    const int n0  = blockIdx.x * GBN;

    float acc[8][8];
#pragma unroll
    for (int i = 0; i < 8; i++)
#pragma unroll
        for (int j = 0; j < 8; j++) acc[i][j] = 0.0f;

    for (int k0 = 0; k0 < K; k0 += GBK) {
        // Load A tile (GBM x GBK) -> As[k][m]
#pragma unroll
        for (int i = tid; i < GBM * GBK; i += 256) {
            int m = i >> 3, k = i & 7;
            As[k][m] = A[(m0 + m) * K + k0 + k];
        }
        // Load B tile (GBK x GBN) -> Bs[k][n]
#pragma unroll
        for (int i = tid; i < GBK * GBN; i += 256) {
            int k = i >> 7, n = i & 127;
            Bs[k][n] = B[(k0 + k) * N + n0 + n];
        }
        __syncthreads();

#pragma unroll
        for (int k = 0; k < GBK; k++) {
            float ra[8], rb[8];
#pragma unroll
            for (int i = 0; i < 8; i++) ra[i] = As[k][ty * 8 + i];
#pragma unroll
            for (int j = 0; j < 8; j++) rb[j] = Bs[k][tx * 8 + j];
#pragma unroll
            for (int i = 0; i < 8; i++)
#pragma unroll
                for (int j = 0; j < 8; j++)
                    acc[i][j] = fmaf(ra[i], rb[j], acc[i][j]);
        }
        __syncthreads();
    }

#pragma unroll
    for (int i = 0; i < 8; i++)
#pragma unroll
        for (int j = 0; j < 8; j++)
            C[(m0 + ty * 8 + i) * N + n0 + tx * 8 + j] = acc[i][j];
}

// ---------------------------------------------------------------------------
// Q: rmsnorm over 256 (per 16-head) then rope on the two 128-subheads.
// grid (TSEQ, 16), 256 threads.
// ---------------------------------------------------------------------------
__global__ void qnorm_rope_kernel(
    const float* __restrict__ q, const float* __restrict__ w,
    const float* __restrict__ sinp, const float* __restrict__ cosp,
    float* __restrict__ out)
{
    const int t = blockIdx.x, h = blockIdx.y;
    const int tid = threadIdx.x;
    __shared__ float buf[256];
    __shared__ float red[8];

    float v = q[t * QDIM + h * 256 + tid];
    float ss = v * v;
#pragma unroll
    for (int o = 16; o > 0; o >>= 1) ss += __shfl_down_sync(0xffffffffu, ss, o);
    if ((tid & 31) == 0) red[tid >> 5] = ss;
    __syncthreads();
    if (tid < 8) {
        float s = red[tid];
#pragma unroll
        for (int o = 4; o > 0; o >>= 1) s += __shfl_down_sync(0xffu, s, o);
        if (tid == 0) red[0] = s;
    }
    __syncthreads();
    float inv = rsqrtf(red[0] * (1.0f / 256.0f) + 1e-6f);
    buf[tid] = v * inv * w[tid];
    __syncthreads();

    int sub = tid >> 7, d = tid & 127;
    const float* base = buf + (sub << 7);
    int j = (d < 64) ? d : d - 64;
    float c = cosp[t * 64 + j], s = sinp[t * 64 + j];
    float x1 = base[2 * j], x2 = base[2 * j + 1];
    float o = (d < 64) ? (x1 * c - x2 * s) : (x1 * s + x2 * c);
    out[t * QDIM + (h * 2 + sub) * HD + d] = o;
}

// ---------------------------------------------------------------------------
// K: rmsnorm over 128 then rope. grid (TSEQ, 8), 128 threads.
// ---------------------------------------------------------------------------
__global__ void knorm_rope_kernel(
    const float* __restrict__ k, const float* __restrict__ w,
    const float* __restrict__ sinp, const float* __restrict__ cosp,
    float* __restrict__ out)
{
    const int t = blockIdx.x, h = blockIdx.y;
    const int tid = threadIdx.x;
    __shared__ float buf[128];
    __shared__ float red[4];

    float v = k[t * KVDIM + h * HD + tid];
    float ss = v * v;
#pragma unroll
    for (int o = 16; o > 0; o >>= 1) ss += __shfl_down_sync(0xffffffffu, ss, o);
    if ((tid & 31) == 0) red[tid >> 5] = ss;
    __syncthreads();
    if (tid < 4) {
        float s = red[tid];
#pragma unroll
        for (int o = 2; o > 0; o >>= 1) s += __shfl_down_sync(0xfu, s, o);
        if (tid == 0) red[0] = s;
    }
    __syncthreads();
    float inv = rsqrtf(red[0] * (1.0f / 128.0f) + 1e-6f);
    buf[tid] = v * inv * w[tid];
    __syncthreads();

    int d = tid;
    int j = (d < 64) ? d : d - 64;
    float c = cosp[t * 64 + j], s = sinp[t * 64 + j];
    float x1 = buf[2 * j], x2 = buf[2 * j + 1];
    float o = (d < 64) ? (x1 * c - x2 * s) : (x1 * s + x2 * c);
    out[t * KVDIM + h * HD + d] = o;
}

// ---------------------------------------------------------------------------
// Flash attention, fp32, non-causal. 64 queries x 1 head per CTA, 256 thr.
// grid (32 q-tiles, 32 heads). Online softmax, K-tiles of 64.
// ---------------------------------------------------------------------------
#define AQ   64
#define AK   64
#define QSTR 129   // 128 + 1 pad
#define SSTR 65    // 64 + 1 pad
#define ATT_SMEM_FLOATS (3 * AQ * QSTR + AQ * SSTR + 3 * AQ)
#define ATT_SMEM_BYTES  (ATT_SMEM_FLOATS * 4)

__global__ __launch_bounds__(256) void attn_kernel(
    const float* __restrict__ Q, const float* __restrict__ K,
    const float* __restrict__ V, float* __restrict__ O)
{
    extern __shared__ float sm[];
    float* Qs   = sm;                    // AQ * QSTR
    float* Ks   = Qs + AQ * QSTR;        // AK * QSTR
    float* Vs   = Ks + AK * QSTR;        // AK * QSTR
    float* Ss   = Vs + AK * QSTR;        // AQ * SSTR
    float* mrow = Ss + AQ * SSTR;        // AQ
    float* lrow = mrow + AQ;             // AQ
    float* arow = lrow + AQ;             // AQ

    const int h   = blockIdx.y;          // 0..31
    const int q0  = blockIdx.x * AQ;
    const int kvh = h >> 2;
    const int tid = threadIdx.x;
    const int tx  = tid & 15, ty = tid >> 4;

    // Load Q tile
    for (int i = tid; i < AQ * HD; i += 256) {
        int r = i >> 7, c = i & 127;
        Qs[r * QSTR + c] = Q[(q0 + r) * QDIM + h * HD + c];
    }
    if (tid < AQ) { mrow[tid] = -1e30f; lrow[tid] = 0.0f; }

    float acc[4][8];
#pragma unroll
    for (int i = 0; i < 4; i++)
#pragma unroll
        for (int j = 0; j < 8; j++) acc[i][j] = 0.0f;

    const float scale = 0.08838834764831845f;  // 1/sqrt(128)

    for (int kt = 0; kt < TSEQ / AK; kt++) {
        const int k0 = kt * AK;
        __syncthreads();   // protect Ks/Vs/Ss reuse (also covers Q-load on iter 0)
        for (int i = tid; i < AK * HD; i += 256) {
            int r = i >> 7, c = i & 127;
            Ks[r * QSTR + c] = K[(k0 + r) * KVDIM + kvh * HD + c];
            Vs[r * QSTR + c] = V[(k0 + r) * KVDIM + kvh * HD + c];
        }
        __syncthreads();

        // S = (Q K^T) * scale ; thread computes 4x4 block
        float s4[4][4];
#pragma unroll
        for (int i = 0; i < 4; i++)
#pragma unroll
            for (int j = 0; j < 4; j++) s4[i][j] = 0.0f;

#pragma unroll 4
        for (int kk = 0; kk < HD; kk++) {
            float ra[4], rb[4];
#pragma unroll
            for (int i = 0; i < 4; i++) ra[i] = Qs[(ty * 4 + i) * QSTR + kk];
#pragma unroll
            for (int j = 0; j < 4; j++) rb[j] = Ks[(tx * 4 + j) * QSTR + kk];
#pragma unroll
            for (int i = 0; i < 4; i++)
#pragma unroll
                for (int j = 0; j < 4; j++)
                    s4[i][j] = fmaf(ra[i], rb[j], s4[i][j]);
        }
#pragma unroll
        for (int i = 0; i < 4; i++)
#pragma unroll
            for (int j = 0; j < 4; j++)
                Ss[(ty * 4 + i) * SSTR + tx * 4 + j] = s4[i][j] * scale;
        __syncthreads();

        // Online softmax, one thread per row
        if (tid < AQ) {
            const int r = tid;
            float m_old = mrow[r];
            float mx = m_old;
            for (int c = 0; c < AK; c++) mx = fmaxf(mx, Ss[r * SSTR + c]);
            float alpha = __expf(m_old - mx);
            float sum = 0.0f;
            for (int c = 0; c < AK; c++) {
                float p = __expf(Ss[r * SSTR + c] - mx);
                Ss[r * SSTR + c] = p;
                sum += p;
            }
            lrow[r] = lrow[r] * alpha + sum;
            mrow[r] = mx;
            arow[r] = alpha;
        }
        __syncthreads();

        // Rescale accumulators, then O += P @ V
#pragma unroll
        for (int i = 0; i < 4; i++) {
            float a = arow[ty * 4 + i];
#pragma unroll
            for (int j = 0; j < 8; j++) acc[i][j] *= a;
        }
#pragma unroll 4
        for (int c = 0; c < AK; c++) {
            float rp[4], rv[8];
#pragma unroll
            for (int i = 0; i < 4; i++) rp[i] = Ss[(ty * 4 + i) * SSTR + c];
#pragma unroll
            for (int j = 0; j < 8; j++) rv[j] = Vs[c * QSTR + tx + 16 * j];
#pragma unroll
            for (int i = 0; i < 4; i++)
#pragma unroll
                for (int j = 0; j < 8; j++)
                    acc[i][j] = fmaf(rp[i], rv[j], acc[i][j]);
        }
    }

    // Normalize and write. Column mapping: col = tx + 16*j
#pragma unroll
    for (int i = 0; i < 4; i++) {
        float inv = 1.0f / lrow[ty * 4 + i];
#pragma unroll
        for (int j = 0; j < 8; j++)
            O[(q0 + ty * 4 + i) * QDIM + h * HD + tx + 16 * j] = acc[i][j] * inv;
    }
}

// ---------------------------------------------------------------------------
// Launch
// ---------------------------------------------------------------------------
extern "C" void kernel_launch(void* const* d_in, const int* in_sizes, int n_in,
                              void* d_out, int out_size)
{
    const float* x    = (const float*)d_in[0];
    const float* Wq   = (const float*)d_in[1];
    const float* Wk   = (const float*)d_in[2];
    const float* Wv   = (const float*)d_in[3];
    const float* Wo   = (const float*)d_in[4];
    const float* qw   = (const float*)d_in[5];
    const float* kw   = (const float*)d_in[6];
    const float* sinp = (const float*)d_in[7];
    const float* cosp = (const float*)d_in[8];
    float* out = (float*)d_out;

    float *pq, *pk, *pv, *pqr, *pkr, *patt;
    cudaGetSymbolAddress((void**)&pq,   g_q);
    cudaGetSymbolAddress((void**)&pk,   g_k);
    cudaGetSymbolAddress((void**)&pv,   g_v);
    cudaGetSymbolAddress((void**)&pqr,  g_qr);
    cudaGetSymbolAddress((void**)&pkr,  g_kr);
    cudaGetSymbolAddress((void**)&patt, g_att);

    // Projections
    sgemm_kernel<<<dim3(QDIM / GBN, TSEQ / GBM), 256>>>(x, Wq, pq, TSEQ, QDIM, HID);
    sgemm_kernel<<<dim3(KVDIM / GBN, TSEQ / GBM), 256>>>(x, Wk, pk, TSEQ, KVDIM, HID);
    sgemm_kernel<<<dim3(KVDIM / GBN, TSEQ / GBM), 256>>>(x, Wv, pv, TSEQ, KVDIM, HID);

    // Norm + rope
    qnorm_rope_kernel<<<dim3(TSEQ, NH16), 256>>>(pq, qw, sinp, cosp, pqr);
    knorm_rope_kernel<<<dim3(TSEQ, NKV), 128>>>(pk, kw, sinp, cosp, pkr);

    // Attention
    cudaFuncSetAttribute(attn_kernel, cudaFuncAttributeMaxDynamicSharedMemorySize,
                         ATT_SMEM_BYTES);
    attn_kernel<<<dim3(TSEQ / AQ, HQ), 256, ATT_SMEM_BYTES>>>(pqr, pkr, pv, patt);

    // Output projection
    sgemm_kernel<<<dim3(HID / GBN, TSEQ / GBM), 256>>>(patt, Wo, out, TSEQ, HID, QDIM);
}

// round 5
// speedup vs baseline: 3.3227x; 3.3227x over previous
#include <cuda_runtime.h>
#include <cstdint>
#include <math.h>

// ---------------------------------------------------------------------------
// Problem constants
// ---------------------------------------------------------------------------
#define TSEQ   2048
#define HID    2048
#define QDIM   4096   // 32 rope-heads * 128
#define KVDIM  1024   // 8 kv heads * 128
#define HD     128
#define NH16   16
#define NKV    8
#define HQ     32

// ---------------------------------------------------------------------------
// Static device scratch (no allocations allowed)
// ---------------------------------------------------------------------------
__device__ float g_q  [TSEQ * QDIM];
__device__ float g_k  [TSEQ * KVDIM];
__device__ float g_v  [TSEQ * KVDIM];
__device__ float g_qr [TSEQ * QDIM];
__device__ float g_kr [TSEQ * KVDIM];
__device__ float g_att[TSEQ * QDIM];
__device__ float g_wqt[QDIM * HID];
__device__ float g_wkt[KVDIM * HID];
__device__ float g_wvt[KVDIM * HID];
__device__ float g_wot[HID * QDIM];
__device__ float g_vt [KVDIM * TSEQ];
__device__ float g_s  [134217728];   // 32 heads * 2048 * 2048 fp32 = 512MB

// ---------------------------------------------------------------------------
// tf32 helpers (base-target PTX only; no tcgen05 — ptxas targets compute_103)
// ---------------------------------------------------------------------------
__device__ __forceinline__ uint32_t f2tf32(float f) {
    uint32_t r;
    asm("cvt.rna.tf32.f32 %0, %1;" : "=r"(r) : "f"(f));
    return r;
}

__device__ __forceinline__ void mma_tf32(
    float& d0, float& d1, float& d2, float& d3,
    uint32_t a0, uint32_t a1, uint32_t a2, uint32_t a3,
    uint32_t b0, uint32_t b1)
{
    asm volatile(
        "mma.sync.aligned.m16n8k8.row.col.f32.tf32.tf32.f32 "
        "{%0,%1,%2,%3}, {%4,%5,%6,%7}, {%8,%9}, {%0,%1,%2,%3};"
        : "+f"(d0), "+f"(d1), "+f"(d2), "+f"(d3)
        : "r"(a0), "r"(a1), "r"(a2), "r"(a3), "r"(b0), "r"(b1));
}

// ---------------------------------------------------------------------------
// mma.sync tf32 GEMM: C[M,N] = A[M,K] @ B[N,K]^T
// A row-major (lda), B row-major [N,K] (ldb) — both K-major, fp32 storage,
// converted to tf32 (round-to-nearest) on the SMEM-store path.
// 128x128 CTA tile, BK=32, 8 warps; warp tile 64x32 = 4x4 m16n8k8 fragments.
// Register-prefetch of next K-chunk overlaps global loads with MMA.
// Batched via blockIdx.z: A += z*bsA, B += (z>>bshift)*bsB, C += z*bsC.
// M, N multiples of 128; K multiple of 32.
// ---------------------------------------------------------------------------
#define BM 128
#define BN 128
#define BK 32
#define ASTR 36   // 32 + 4 pad (floats)

__global__ __launch_bounds__(256) void gemm_mma(
    const float* __restrict__ A, const float* __restrict__ B,
    float* __restrict__ C, int K, int lda, int ldb, int ldc,
    long long bsA, long long bsB, long long bsC, int bshift)
{
    __shared__ uint32_t As[BM][ASTR];
    __shared__ uint32_t Bs[BN][ASTR];

    const int z = blockIdx.z;
    A += (long long)z * bsA;
    B += (long long)(z >> bshift) * bsB;
    C += (long long)z * bsC;

    const int tid  = threadIdx.x;
    const int wid  = tid >> 5;
    const int lane = tid & 31;
    const int m0 = blockIdx.y * BM;
    const int n0 = blockIdx.x * BN;

    const int wm = (wid >> 2) * 64;   // warp M offset: 0 / 64
    const int wn = (wid & 3) * 32;    // warp N offset: 0/32/64/96
    const int g  = lane >> 2;         // 0..7
    const int t  = lane & 3;          // 0..3

    float acc[4][4][4];
#pragma unroll
    for (int mt = 0; mt < 4; mt++)
#pragma unroll
        for (int nt = 0; nt < 4; nt++)
#pragma unroll
            for (int r = 0; r < 4; r++) acc[mt][nt][r] = 0.0f;

    // Global-load mapping: thread covers rows r0+32p, float4 column c4
    const int r0 = tid >> 3;
    const int c4 = (tid & 7) << 2;

    float4 pa[4], pb[4];
#pragma unroll
    for (int p = 0; p < 4; p++) {
        const int row = r0 + (p << 5);
        pa[p] = *(const float4*)(A + (size_t)(m0 + row) * lda + c4);
        pb[p] = *(const float4*)(B + (size_t)(n0 + row) * ldb + c4);
    }
#pragma unroll
    for (int p = 0; p < 4; p++) {
        const int row = r0 + (p << 5);
        As[row][c4 + 0] = f2tf32(pa[p].x);
        As[row][c4 + 1] = f2tf32(pa[p].y);
        As[row][c4 + 2] = f2tf32(pa[p].z);
        As[row][c4 + 3] = f2tf32(pa[p].w);
        Bs[row][c4 + 0] = f2tf32(pb[p].x);
        Bs[row][c4 + 1] = f2tf32(pb[p].y);
        Bs[row][c4 + 2] = f2tf32(pb[p].z);
        Bs[row][c4 + 3] = f2tf32(pb[p].w);
    }
    __syncthreads();

    const int nk = K >> 5;
    for (int kt = 0; kt < nk; kt++) {
        // Prefetch next K-chunk into registers (overlaps with MMA below)
        if (kt + 1 < nk) {
            const int k0 = (kt + 1) << 5;
#pragma unroll
            for (int p = 0; p < 4; p++) {
                const int row = r0 + (p << 5);
                pa[p] = *(const float4*)(A + (size_t)(m0 + row) * lda + k0 + c4);
                pb[p] = *(const float4*)(B + (size_t)(n0 + row) * ldb + k0 + c4);
            }
        }

        // Compute on current SMEM tile
#pragma unroll
        for (int ks = 0; ks < 4; ks++) {
            const int k = ks << 3;
            uint32_t af[4][4], bf[4][2];
#pragma unroll
            for (int mt = 0; mt < 4; mt++) {
                const int r = wm + mt * 16 + g;
                af[mt][0] = As[r    ][k + t];
                af[mt][1] = As[r + 8][k + t];
                af[mt][2] = As[r    ][k + t + 4];
                af[mt][3] = As[r + 8][k + t + 4];
            }
#pragma unroll
            for (int nt = 0; nt < 4; nt++) {
                const int r = wn + nt * 8 + g;
                bf[nt][0] = Bs[r][k + t];
                bf[nt][1] = Bs[r][k + t + 4];
            }
#pragma unroll
            for (int mt = 0; mt < 4; mt++)
#pragma unroll
                for (int nt = 0; nt < 4; nt++)
                    mma_tf32(acc[mt][nt][0], acc[mt][nt][1],
                             acc[mt][nt][2], acc[mt][nt][3],
                             af[mt][0], af[mt][1], af[mt][2], af[mt][3],
                             bf[nt][0], bf[nt][1]);
        }
        __syncthreads();

        if (kt + 1 < nk) {
#pragma unroll
            for (int p = 0; p < 4; p++) {
                const int row = r0 + (p << 5);
                As[row][c4 + 0] = f2tf32(pa[p].x);
                As[row][c4 + 1] = f2tf32(pa[p].y);
                As[row][c4 + 2] = f2tf32(pa[p].z);
                As[row][c4 + 3] = f2tf32(pa[p].w);
                Bs[row][c4 + 0] = f2tf32(pb[p].x);
                Bs[row][c4 + 1] = f2tf32(pb[p].y);
                Bs[row][c4 + 2] = f2tf32(pb[p].z);
                Bs[row][c4 + 3] = f2tf32(pb[p].w);
            }
            __syncthreads();
        }
    }

    // Epilogue: c0,c1 at (row, 2t), c2,c3 at (row+8, 2t)
#pragma unroll
    for (int mt = 0; mt < 4; mt++) {
        const int row = m0 + wm + mt * 16 + g;
#pragma unroll
        for (int nt = 0; nt < 4; nt++) {
            const int col = n0 + wn + nt * 8 + 2 * t;
            *(float2*)(C + (size_t)row * ldc + col) =
                make_float2(acc[mt][nt][0], acc[mt][nt][1]);
            *(float2*)(C + (size_t)(row + 8) * ldc + col) =
                make_float2(acc[mt][nt][2], acc[mt][nt][3]);
        }
    }
}

// ---------------------------------------------------------------------------
// Tiled transpose: out[C][R] = in[R][C]^T   (R, C multiples of 32)
// ---------------------------------------------------------------------------
__global__ void transpose_kernel(const float* __restrict__ in,
                                 float* __restrict__ out, int R, int C)
{
    __shared__ float t[32][33];
    const int x = blockIdx.x * 32 + threadIdx.x;   // col in
    const int y0 = blockIdx.y * 32 + threadIdx.y;  // row in
#pragma unroll
    for (int j = 0; j < 32; j += 8)
        t[threadIdx.y + j][threadIdx.x] = in[(size_t)(y0 + j) * C + x];
    __syncthreads();
    const int x2 = blockIdx.y * 32 + threadIdx.x;  // col out (= row in)
    const int y2 = blockIdx.x * 32 + threadIdx.y;  // row out (= col in)
#pragma unroll
    for (int j = 0; j < 32; j += 8)
        out[(size_t)(y2 + j) * R + x2] = t[threadIdx.x][threadIdx.y + j];
}

// ---------------------------------------------------------------------------
// Row softmax with scale, in place. One warp per row of 2048.
// ---------------------------------------------------------------------------
__global__ __launch_bounds__(256) void softmax_kernel(float* __restrict__ S)
{
    const float scale = 0.08838834764831845f;  // 1/sqrt(128)
    const int row = blockIdx.x * 8 + (threadIdx.x >> 5);
    const int lane = threadIdx.x & 31;
    float* p = S + (size_t)row * 2048 + lane * 4;

    float4 v[16];
#pragma unroll
    for (int w = 0; w < 16; w++) v[w] = *(const float4*)(p + w * 128);

    float m = -1e30f;
#pragma unroll
    for (int w = 0; w < 16; w++)
        m = fmaxf(m, fmaxf(fmaxf(v[w].x, v[w].y), fmaxf(v[w].z, v[w].w)));
#pragma unroll
    for (int o = 16; o > 0; o >>= 1)
        m = fmaxf(m, __shfl_xor_sync(0xffffffffu, m, o));

    const float ms = m * scale;
    float sum = 0.0f;
#pragma unroll
    for (int w = 0; w < 16; w++) {
        v[w].x = __expf(fmaf(v[w].x, scale, -ms));
        v[w].y = __expf(fmaf(v[w].y, scale, -ms));
        v[w].z = __expf(fmaf(v[w].z, scale, -ms));
        v[w].w = __expf(fmaf(v[w].w, scale, -ms));
        sum += v[w].x + v[w].y + v[w].z + v[w].w;
    }
#pragma unroll
    for (int o = 16; o > 0; o >>= 1)
        sum += __shfl_xor_sync(0xffffffffu, sum, o);

    const float inv = 1.0f / sum;
#pragma unroll
    for (int w = 0; w < 16; w++) {
        v[w].x *= inv; v[w].y *= inv; v[w].z *= inv; v[w].w *= inv;
        *(float4*)(p + w * 128) = v[w];
    }
}

// ---------------------------------------------------------------------------
// Q rmsnorm (over 256) + rope. grid (TSEQ, 16), 256 threads.
// ---------------------------------------------------------------------------
__global__ void qnorm_rope_kernel(
    const float* __restrict__ q, const float* __restrict__ w,
    const float* __restrict__ sinp, const float* __restrict__ cosp,
    float* __restrict__ out)
{
    const int t = blockIdx.x, h = blockIdx.y;
    const int tid = threadIdx.x;
    __shared__ float buf[256];
    __shared__ float red[8];

    float v = q[t * QDIM + h * 256 + tid];
    float ss = v * v;
#pragma unroll
    for (int o = 16; o > 0; o >>= 1) ss += __shfl_down_sync(0xffffffffu, ss, o);
    if ((tid & 31) == 0) red[tid >> 5] = ss;
    __syncthreads();
    if (tid < 8) {
        float s = red[tid];
#pragma unroll
        for (int o = 4; o > 0; o >>= 1) s += __shfl_down_sync(0xffu, s, o);
        if (tid == 0) red[0] = s;
    }
    __syncthreads();
    float inv = rsqrtf(red[0] * (1.0f / 256.0f) + 1e-6f);
    buf[tid] = v * inv * w[tid];
    __syncthreads();

    int sub = tid >> 7, d = tid & 127;
    const float* base = buf + (sub << 7);
    int j = (d < 64) ? d : d - 64;
    float c = cosp[t * 64 + j], s = sinp[t * 64 + j];
    float x1 = base[2 * j], x2 = base[2 * j + 1];
    float o = (d < 64) ? (x1 * c - x2 * s) : (x1 * s + x2 * c);
    out[t * QDIM + (h * 2 + sub) * HD + d] = o;
}

// ---------------------------------------------------------------------------
// K rmsnorm (over 128) + rope. grid (TSEQ, 8), 128 threads.
// ---------------------------------------------------------------------------
__global__ void knorm_rope_kernel(
    const float* __restrict__ k, const float* __restrict__ w,
    const float* __restrict__ sinp, const float* __restrict__ cosp,
    float* __restrict__ out)
{
    const int t = blockIdx.x, h = blockIdx.y;
    const int tid = threadIdx.x;
    __shared__ float buf[128];
    __shared__ float red[4];

    float v = k[t * KVDIM + h * HD + tid];
    float ss = v * v;
#pragma unroll
    for (int o = 16; o > 0; o >>= 1) ss += __shfl_down_sync(0xffffffffu, ss, o);
    if ((tid & 31) == 0) red[tid >> 5] = ss;
    __syncthreads();
    if (tid < 4) {
        float s = red[tid];
#pragma unroll
        for (int o = 2; o > 0; o >>= 1) s += __shfl_down_sync(0xfu, s, o);
        if (tid == 0) red[0] = s;
    }
    __syncthreads();
    float inv = rsqrtf(red[0] * (1.0f / 128.0f) + 1e-6f);
    buf[tid] = v * inv * w[tid];
    __syncthreads();

    int d = tid;
    int j = (d < 64) ? d : d - 64;
    float c = cosp[t * 64 + j], s = sinp[t * 64 + j];
    float x1 = buf[2 * j], x2 = buf[2 * j + 1];
    float o = (d < 64) ? (x1 * c - x2 * s) : (x1 * s + x2 * c);
    out[t * KVDIM + h * HD + d] = o;
}

// ---------------------------------------------------------------------------
// Launch
// ---------------------------------------------------------------------------
extern "C" void kernel_launch(void* const* d_in, const int* in_sizes, int n_in,
                              void* d_out, int out_size)
{
    const float* x    = (const float*)d_in[0];
    const float* Wq   = (const float*)d_in[1];
    const float* Wk   = (const float*)d_in[2];
    const float* Wv   = (const float*)d_in[3];
    const float* Wo   = (const float*)d_in[4];
    const float* qw   = (const float*)d_in[5];
    const float* kw   = (const float*)d_in[6];
    const float* sinp = (const float*)d_in[7];
    const float* cosp = (const float*)d_in[8];
    float* out = (float*)d_out;

    float *pq, *pk, *pv, *pqr, *pkr, *patt;
    float *pwqt, *pwkt, *pwvt, *pwot, *pvt, *ps;
    cudaGetSymbolAddress((void**)&pq,   g_q);
    cudaGetSymbolAddress((void**)&pk,   g_k);
    cudaGetSymbolAddress((void**)&pv,   g_v);
    cudaGetSymbolAddress((void**)&pqr,  g_qr);
    cudaGetSymbolAddress((void**)&pkr,  g_kr);
    cudaGetSymbolAddress((void**)&patt, g_att);
    cudaGetSymbolAddress((void**)&pwqt, g_wqt);
    cudaGetSymbolAddress((void**)&pwkt, g_wkt);
    cudaGetSymbolAddress((void**)&pwvt, g_wvt);
    cudaGetSymbolAddress((void**)&pwot, g_wot);
    cudaGetSymbolAddress((void**)&pvt,  g_vt);
    cudaGetSymbolAddress((void**)&ps,   g_s);

    dim3 tb(32, 8);
    // Weight transposes to [N,K] K-major
    transpose_kernel<<<dim3(QDIM / 32, HID / 32), tb>>>(Wq, pwqt, HID, QDIM);
    transpose_kernel<<<dim3(KVDIM / 32, HID / 32), tb>>>(Wk, pwkt, HID, KVDIM);
    transpose_kernel<<<dim3(KVDIM / 32, HID / 32), tb>>>(Wv, pwvt, HID, KVDIM);
    transpose_kernel<<<dim3(HID / 32, QDIM / 32), tb>>>(Wo, pwot, QDIM, HID);

    // Projections
    gemm_mma<<<dim3(QDIM / BN, TSEQ / BM, 1), 256>>>(
        x, pwqt, pq, HID, HID, HID, QDIM, 0, 0, 0, 0);
    gemm_mma<<<dim3(KVDIM / BN, TSEQ / BM, 1), 256>>>(
        x, pwkt, pk, HID, HID, HID, KVDIM, 0, 0, 0, 0);
    gemm_mma<<<dim3(KVDIM / BN, TSEQ / BM, 1), 256>>>(
        x, pwvt, pv, HID, HID, HID, KVDIM, 0, 0, 0, 0);

    // Norm + rope
    qnorm_rope_kernel<<<dim3(TSEQ, NH16), 256>>>(pq, qw, sinp, cosp, pqr);
    knorm_rope_kernel<<<dim3(TSEQ, NKV), 128>>>(pk, kw, sinp, cosp, pkr);

    // V^T for PV gemm
    transpose_kernel<<<dim3(KVDIM / 32, TSEQ / 32), tb>>>(pv, pvt, TSEQ, KVDIM);

    // S = Q K^T per head (raw logits), batched over 32 heads
    gemm_mma<<<dim3(TSEQ / BN, TSEQ / BM, HQ), 256>>>(
        pqr, pkr, ps, HD, QDIM, KVDIM, TSEQ,
        (long long)HD, (long long)HD, (long long)TSEQ * TSEQ, 2);

    // softmax rows (scale folded in)
    softmax_kernel<<<(HQ * TSEQ) / 8, 256>>>(ps);

    // O = P V per head
    gemm_mma<<<dim3(HD / BN, TSEQ / BM, HQ), 256>>>(
        ps, pvt, patt, TSEQ, TSEQ, TSEQ, QDIM,
        (long long)TSEQ * TSEQ, (long long)HD * TSEQ, (long long)HD, 2);

    // Output projection
    gemm_mma<<<dim3(HID / BN, TSEQ / BM, 1), 256>>>(
        patt, pwot, out, QDIM, QDIM, QDIM, HID, 0, 0, 0, 0);
}